// round 12
// baseline (speedup 1.0000x reference)
#include <cuda_runtime.h>

// SR_Loss: NN(obj->sr) + ray-triangle parity interior test + reductions.
// obj 8192x3, sr 4096x3, verts 4100x3, normals 4096x3, faces 4096x3.
// Output: [pen_dist, cmap(8192)] = 8193 f32.
//
// 2 kernels:
//  prep_nn : blocks 0-15 build face constants (28 f/pair, edge-C eliminated)
//            + zero counters; blocks 16-143 do NN (8 points/warp) -> g_D4 +
//            cmap (reads raw sr; no dependency on prep blocks).
//  hits    : 2048 blocks = 256 point-groups x 8 face-slices; smem-tiled face
//            records, f32x2 packed sign tests; int atomics for hit counts;
//            group-last computes pen partial; global-last reduces pen_dist.

#define N_OBJ  8192
#define N_SR   4096
#define N_F    4096
#define NPAIR  (N_F / 2)          // 2048
#define EPSF   1e-8f
#define NGRP   (N_OBJ / 32)       // 256 point groups
#define NFQ    8                  // face slices per group
#define PAIRS_PER_FQ (NPAIR / NFQ) // 256

#define TILE_P     128
#define NTILE_FQ   (PAIRS_PER_FQ / TILE_P)   // 2
#define REC_U      7                          // ulonglong2 per pair record
#define TILE_BYTES (TILE_P * REC_U * 16)      // 14336
#define CHUNKS     (TILE_BYTES / 16)          // 896

#define PREP_BLKS  16
#define PTS_PER_WARP 8
#define PTS_PER_BLK  (PTS_PER_WARP * 8)      // 64
#define NN_BLKS    (N_OBJ / PTS_PER_BLK)     // 128

typedef unsigned long long u64;

// ---------------- scratch (device globals; no allocation allowed) ----------
__device__ float4 g_face4[NPAIR * REC_U];   // pair-interleaved records (28 f/pair)
__device__ float4 g_D4[N_OBJ];              // D = trg - o, .w = |D|^2
__device__ int    g_hits[N_OBJ];            // accumulated hit counts
__device__ float  g_part[NGRP];             // per-group pen partials
__device__ unsigned int g_gctr[NGRP];       // per-group arrival counters
__device__ unsigned int g_ctr;              // global arrival counter

// ---------------- f32x2 packed helpers (sm_103a) ---------------------------
__device__ __forceinline__ u64 pk(float lo, float hi) {
    u64 r;
    asm("mov.b64 %0, {%1, %2};" : "=l"(r)
        : "r"(__float_as_uint(lo)), "r"(__float_as_uint(hi)));
    return r;
}
__device__ __forceinline__ void upku(u64 v, unsigned int& lo, unsigned int& hi) {
    asm("mov.b64 {%0, %1}, %2;" : "=r"(lo), "=r"(hi) : "l"(v));
}
__device__ __forceinline__ u64 f2mul(u64 a, u64 b) {
    u64 r;
    asm("mul.rn.f32x2 %0, %1, %2;" : "=l"(r) : "l"(a), "l"(b));
    return r;
}
__device__ __forceinline__ u64 f2add(u64 a, u64 b) {
    u64 r;
    asm("add.rn.f32x2 %0, %1, %2;" : "=l"(r) : "l"(a), "l"(b));
    return r;
}
__device__ __forceinline__ u64 f2fma(u64 a, u64 b, u64 c) {
    u64 r;
    asm("fma.rn.f32x2 %0, %1, %2, %3;" : "=l"(r) : "l"(a), "l"(b), "l"(c));
    return r;
}
__device__ __forceinline__ void cp16(unsigned int saddr, const void* gaddr) {
    asm volatile("cp.async.cg.shared.global [%0], [%1], 16;"
                 :: "r"(saddr), "l"(gaddr));
}
__device__ __forceinline__ unsigned int smem_u32(const void* p) {
    return (unsigned int)__cvta_generic_to_shared(p);
}

// ---------------- prep_nn --------------------------------------------------
// Pair record, 14 slots of f32x2 (28 floats, 112B):
//  q0-2: n, q3: v0.n, q4-6: C01, q7: e01, q8-10: C12, q11: e12,
//  q12: E = e01+e12+e20, q13: pad.   (C20 = -(C01+C12) by identity.)
__global__ void __launch_bounds__(256) prep_nn_kernel(const float* __restrict__ sr,
                                                      const float* __restrict__ hv,
                                                      const float* __restrict__ fn,
                                                      const int*   __restrict__ hf,
                                                      const float* __restrict__ obj,
                                                      float* __restrict__ out) {
    if (blockIdx.x < PREP_BLKS) {
        // ---------------- prep part ----------------
        int f = blockIdx.x * 256 + threadIdx.x;   // 0..4095
        if (f == 0) g_ctr = 0;
        if (f < NGRP) g_gctr[f] = 0;
        g_hits[f] = 0;
        g_hits[f + N_F] = 0;

        int i0 = hf[3 * f + 0], i1 = hf[3 * f + 1], i2 = hf[3 * f + 2];
        float nx = fn[3 * f + 0], ny = fn[3 * f + 1], nz = fn[3 * f + 2];
        float v0x = hv[3 * i0 + 0], v0y = hv[3 * i0 + 1], v0z = hv[3 * i0 + 2];
        float v1x = hv[3 * i1 + 0], v1y = hv[3 * i1 + 1], v1z = hv[3 * i1 + 2];
        float v2x = hv[3 * i2 + 0], v2y = hv[3 * i2 + 1], v2z = hv[3 * i2 + 2];

        float vals[14];
        vals[0] = nx; vals[1] = ny; vals[2] = nz;
        vals[3] = v0x * nx + v0y * ny + v0z * nz;

        float eA, eB, eC;
        {   // edge 01
            float wx = v1x - v0x, wy = v1y - v0y, wz = v1z - v0z;
            float cx = ny * wz - nz * wy, cy = nz * wx - nx * wz, cz = nx * wy - ny * wx;
            vals[4] = cx; vals[5] = cy; vals[6] = cz;
            eA = -(v0x * cx + v0y * cy + v0z * cz);
            vals[7] = eA;
        }
        {   // edge 12
            float wx = v2x - v1x, wy = v2y - v1y, wz = v2z - v1z;
            float cx = ny * wz - nz * wy, cy = nz * wx - nx * wz, cz = nx * wy - ny * wx;
            vals[8] = cx; vals[9] = cy; vals[10] = cz;
            eB = -(v1x * cx + v1y * cy + v1z * cz);
            vals[11] = eB;
        }
        {   // edge 20 (only its offset is needed)
            float wx = v0x - v2x, wy = v0y - v2y, wz = v0z - v2z;
            float cx = ny * wz - nz * wy, cy = nz * wx - nx * wz, cz = nx * wy - ny * wx;
            eC = -(v2x * cx + v2y * cy + v2z * cz);
        }
        vals[12] = eA + eB + eC;
        vals[13] = 0.0f;

        int p = f >> 1, h = f & 1;
        float* o = reinterpret_cast<float*>(g_face4) + p * 28 + h;
#pragma unroll
        for (int q = 0; q < 14; q++) o[2 * q] = vals[q];
        return;
    }

    // ---------------- nn part: 8 points per warp ----------------------------
    int wid = threadIdx.x >> 5, lane = threadIdx.x & 31;
    int pbase = (blockIdx.x - PREP_BLKS) * PTS_PER_BLK + wid * PTS_PER_WARP;

    float ox[PTS_PER_WARP], oy[PTS_PER_WARP], oz[PTS_PER_WARP], o2[PTS_PER_WARP];
    float bb[PTS_PER_WARP];
    int   jj[PTS_PER_WARP];
#pragma unroll
    for (int k = 0; k < PTS_PER_WARP; k++) {
        ox[k] = obj[3 * (pbase + k) + 0];
        oy[k] = obj[3 * (pbase + k) + 1];
        oz[k] = obj[3 * (pbase + k) + 2];
        o2[k] = ox[k] * ox[k] + oy[k] * oy[k] + oz[k] * oz[k];
        bb[k] = 3.402823466e38f;
        jj[k] = 0;
    }

#pragma unroll 2
    for (int j = lane; j < N_SR; j += 32) {
        float sx = __ldg(&sr[3 * j + 0]);
        float sy = __ldg(&sr[3 * j + 1]);
        float sz = __ldg(&sr[3 * j + 2]);
        float s2 = sx * sx + sy * sy + sz * sz;
#pragma unroll
        for (int k = 0; k < PTS_PER_WARP; k++) {
            float d = fmaf(-2.0f, ox[k] * sx + fmaf(oy[k], sy, oz[k] * sz), o2[k] + s2);
            if (d < bb[k]) { bb[k] = d; jj[k] = j; }
        }
    }
#pragma unroll
    for (int off = 16; off; off >>= 1) {
#pragma unroll
        for (int k = 0; k < PTS_PER_WARP; k++) {
            float t = __shfl_down_sync(~0u, bb[k], off);
            int  tj = __shfl_down_sync(~0u, jj[k], off);
            if (t < bb[k] || (t == bb[k] && tj < jj[k])) { bb[k] = t; jj[k] = tj; }
        }
    }

    if (lane == 0) {
#pragma unroll
        for (int k = 0; k < PTS_PER_WARP; k++) {
            float sx = sr[3 * jj[k] + 0], sy = sr[3 * jj[k] + 1], sz = sr[3 * jj[k] + 2];
            float Dx = sx - ox[k], Dy = sy - oy[k], Dz = sz - oz[k];
            g_D4[pbase + k] = make_float4(Dx, Dy, Dz, Dx * Dx + Dy * Dy + Dz * Dz);
            float nnd = sqrtf(fmaxf(bb[k], 0.0f));
            out[1 + pbase + k] = 2.0f / (1.0f + expf(100.0f * nnd));
        }
    }
}

// ---------------- hits: parity + reductions --------------------------------
// Block = (group, slice): 32 points (lane=point) x 256 face-pairs.
__global__ void __launch_bounds__(256, 4) hits_kernel(const float* __restrict__ obj,
                                                      float* __restrict__ out) {
    __shared__ __align__(16) char s_face[2][TILE_BYTES];   // 2 x 14 KB
    __shared__ int    s_cnt[8][32];
    __shared__ int    s_glast, s_last;
    __shared__ float  s_red[256];

    int tid = threadIdx.x;
    int wid = tid >> 5, lane = tid & 31;
    int grp = blockIdx.x >> 3, fq = blockIdx.x & 7;
    int pt  = grp * 32 + lane;

    float ox = obj[3 * pt + 0], oy = obj[3 * pt + 1], oz = obj[3 * pt + 2];
    float4 D = __ldg(&g_D4[pt]);

    u64 OX = pk(ox, ox), OY = pk(oy, oy), OZ = pk(oz, oz);
    u64 DX = pk(D.x, D.x), DY = pk(D.y, D.y), DZ = pk(D.z, D.z);
    u64 NEG1 = pk(-1.0f, -1.0f);
    u64 MEPS = pk(-EPSF, -EPSF);
    const unsigned int EPS_BITS = __float_as_uint(EPSF);
    const unsigned int SGN = 0x80000000u;

    const char* gfb = reinterpret_cast<const char*>(g_face4)
                      + (size_t)fq * PAIRS_PER_FQ * REC_U * 16;

    // stage tile 0
    {
        unsigned int sb = smem_u32(&s_face[0][0]);
#pragma unroll
        for (int k = 0; k < 4; k++) {
            int idx = tid + k * 256;
            if (idx < CHUNKS) cp16(sb + idx * 16, gfb + idx * 16);
        }
        asm volatile("cp.async.commit_group;" ::: "memory");
    }

    int cnt = 0;

    for (int t = 0; t < NTILE_FQ; t++) {
        if (t + 1 < NTILE_FQ) {
            unsigned int sb = smem_u32(&s_face[(t + 1) & 1][0]);
            const char* gsrc = gfb + (t + 1) * TILE_BYTES;
#pragma unroll
            for (int k = 0; k < 4; k++) {
                int idx = tid + k * 256;
                if (idx < CHUNKS) cp16(sb + idx * 16, gsrc + idx * 16);
            }
            asm volatile("cp.async.commit_group;" ::: "memory");
            asm volatile("cp.async.wait_group 1;" ::: "memory");
        } else {
            asm volatile("cp.async.wait_group 0;" ::: "memory");
        }
        __syncthreads();

        const ulonglong2* up = reinterpret_cast<const ulonglong2*>(
            &s_face[t & 1][0]) + (wid * (TILE_P / 8)) * REC_U;

#pragma unroll 4
        for (int lp = 0; lp < TILE_P / 8; lp++, up += REC_U) {
            ulonglong2 t0 = up[0];   // nx | ny
            ulonglong2 t1 = up[1];   // nz | v0n
            ulonglong2 t2 = up[2];   // CAx | CAy
            ulonglong2 t3 = up[3];   // CAz | eA
            ulonglong2 t4 = up[4];   // CBx | CBy
            ulonglong2 t5 = up[5];   // CBz | eB
            u64 Ev = up[6].x;        // E (f32x2)

            // normal block
            u64 no   = f2fma(t0.x, OX, f2fma(t0.y, OY, f2mul(t1.x, OZ)));
            u64 num  = f2fma(no, NEG1, t1.y);      // v0n - n.o
            u64 den  = f2fma(t0.x, DX, f2fma(t0.y, DY, f2mul(t1.x, DZ)));

            // edge A
            u64 ba = f2fma(t2.x, OX, f2fma(t2.y, OY, f2fma(t3.x, OZ, t3.y)));
            u64 da = f2fma(t2.x, DX, f2fma(t2.y, DY, f2mul(t3.x, DZ)));
            u64 qa = f2fma(ba, den, f2mul(num, da));

            // edge B
            u64 bb_ = f2fma(t4.x, OX, f2fma(t4.y, OY, f2fma(t5.x, OZ, t5.y)));
            u64 db  = f2fma(t4.x, DX, f2fma(t4.y, DY, f2mul(t5.x, DZ)));
            u64 qb  = f2fma(bb_, den, f2mul(num, db));

            // edge C (negated) by identity: C20 = -(C01+C12), e-sum E.
            //   qcn = (ba + bb - E)*den + num*(da+db) = -qc
            // sign(qc)==sign(den)  <=>  sign(qcn)==sign(-den)
            u64 sab = f2add(da, db);
            u64 tab = f2add(ba, bb_);
            u64 nbc = f2fma(Ev, NEG1, tab);               // tab - E
            u64 qcn = f2fma(nbc, den, f2mul(num, sab));

            // w = num - EPS*den
            u64 wv = f2fma(MEPS, den, num);

            unsigned int qa0, qa1, qb0, qb1, qc0, qc1, w0, w1, d0, d1;
            upku(qa, qa0, qa1);
            upku(qb, qb0, qb1);
            upku(qcn, qc0, qc1);
            upku(wv, w0, w1);
            upku(den, d0, d1);

            unsigned int dn0 = d0 ^ SGN, dn1 = d1 ^ SGN;
            unsigned int x0 = ((qa0 ^ d0) | (qb0 ^ d0)) | ((qc0 ^ dn0) | (w0 ^ d0));
            unsigned int x1 = ((qa1 ^ d1) | (qb1 ^ d1)) | ((qc1 ^ dn1) | (w1 ^ d1));
            cnt += (int)(((int)x0 >= 0) & ((d0 & 0x7fffffffu) > EPS_BITS));
            cnt += (int)(((int)x1 >= 0) & ((d1 & 0x7fffffffu) > EPS_BITS));
        }
        __syncthreads();
    }

    s_cnt[wid][lane] = cnt;
    __syncthreads();

    // warp 0 accumulates this block's per-point counts into gmem (int = exact)
    if (wid == 0) {
        int tot = 0;
#pragma unroll
        for (int k = 0; k < 8; k++) tot += s_cnt[k][lane];
        atomicAdd(&g_hits[pt], tot);
    }

    // group completion
    if (tid == 0) {
        __threadfence();
        unsigned int a = atomicAdd(&g_gctr[grp], 1u);
        s_glast = (a == NFQ - 1) ? 1 : 0;
        s_last = 0;
    }
    __syncthreads();

    if (s_glast) {
        if (wid == 0) {
            int tot;
            asm volatile("ld.global.cg.s32 %0, [%1];" : "=r"(tot)
                         : "l"(&g_hits[pt]));
            float dw;
            asm volatile("ld.global.cg.f32 %0, [%1];" : "=f"(dw)
                         : "l"(reinterpret_cast<const float*>(&g_D4[pt]) + 3));
            float pen = (tot & 1) ? dw : 0.0f;
#pragma unroll
            for (int off = 16; off; off >>= 1)
                pen += __shfl_down_sync(~0u, pen, off);
            if (lane == 0) {
                g_part[grp] = pen;
                __threadfence();
                unsigned int a = atomicAdd(&g_ctr, 1u);
                if (a == NGRP - 1) s_last = 1;
            }
        }
        __syncthreads();

        if (s_last) {
            float v;
            asm volatile("ld.global.cg.f32 %0, [%1];" : "=f"(v)
                         : "l"(&g_part[tid]));
            s_red[tid] = v;
            __syncthreads();
#pragma unroll
            for (int off = 128; off; off >>= 1) {
                if (tid < off) s_red[tid] += s_red[tid + off];
                __syncthreads();
            }
            if (tid == 0) out[0] = sqrtf(s_red[0] + 1e-12f);
        }
    }
}

// ---------------- launch ---------------------------------------------------
extern "C" void kernel_launch(void* const* d_in, const int* in_sizes, int n_in,
                              void* d_out, int out_size) {
    const float* obj = (const float*)d_in[0];
    const float* sr  = (const float*)d_in[1];
    const float* hv  = (const float*)d_in[2];
    const float* fn  = (const float*)d_in[3];
    const int*   hf  = (const int*)d_in[4];
    float* out = (float*)d_out;

    prep_nn_kernel<<<PREP_BLKS + NN_BLKS, 256>>>(sr, hv, fn, hf, obj, out);
    hits_kernel<<<NGRP * NFQ, 256>>>(obj, out);
}

// round 13
// speedup vs baseline: 1.2961x; 1.2961x over previous
#include <cuda_runtime.h>

// SR_Loss: NN(obj->sr) + ray-triangle parity interior test + reductions.
// obj 8192x3, sr 4096x3, verts 4100x3, normals 4096x3, faces 4096x3.
// Output: [pen_dist, cmap(8192)] = 8193 f32.
//
// 2 kernels:
//  prep_nn : blocks 0-15 build face constants (28 f/pair, edge-C eliminated)
//            + zero counters; blocks 16-527 do NN (2 points/warp) -> g_D4 +
//            cmap (reads raw sr; no dependency on prep blocks).
//  hits    : 2048 blocks = 256 point-groups x 8 face-slices; smem-tiled face
//            records, f32x2 packed sign tests; int atomics for hit counts;
//            group-last computes pen partial; global-last reduces pen_dist.
//            launch_bounds(256,5) to lift the register-limited occupancy cap.

#define N_OBJ  8192
#define N_SR   4096
#define N_F    4096
#define NPAIR  (N_F / 2)          // 2048
#define EPSF   1e-8f
#define NGRP   (N_OBJ / 32)       // 256 point groups
#define NFQ    8                  // face slices per group
#define PAIRS_PER_FQ (NPAIR / NFQ) // 256

#define TILE_P     128
#define NTILE_FQ   (PAIRS_PER_FQ / TILE_P)   // 2
#define REC_U      7                          // ulonglong2 per pair record
#define TILE_BYTES (TILE_P * REC_U * 16)      // 14336
#define CHUNKS     (TILE_BYTES / 16)          // 896

#define PREP_BLKS  16
#define NN_BLKS    512

typedef unsigned long long u64;

// ---------------- scratch (device globals; no allocation allowed) ----------
__device__ float4 g_face4[NPAIR * REC_U];   // pair-interleaved records (28 f/pair)
__device__ float4 g_D4[N_OBJ];              // D = trg - o, .w = |D|^2
__device__ int    g_hits[N_OBJ];            // accumulated hit counts
__device__ float  g_part[NGRP];             // per-group pen partials
__device__ unsigned int g_gctr[NGRP];       // per-group arrival counters
__device__ unsigned int g_ctr;              // global arrival counter

// ---------------- f32x2 packed helpers (sm_103a) ---------------------------
__device__ __forceinline__ u64 pk(float lo, float hi) {
    u64 r;
    asm("mov.b64 %0, {%1, %2};" : "=l"(r)
        : "r"(__float_as_uint(lo)), "r"(__float_as_uint(hi)));
    return r;
}
__device__ __forceinline__ void upku(u64 v, unsigned int& lo, unsigned int& hi) {
    asm("mov.b64 {%0, %1}, %2;" : "=r"(lo), "=r"(hi) : "l"(v));
}
__device__ __forceinline__ u64 f2mul(u64 a, u64 b) {
    u64 r;
    asm("mul.rn.f32x2 %0, %1, %2;" : "=l"(r) : "l"(a), "l"(b));
    return r;
}
__device__ __forceinline__ u64 f2add(u64 a, u64 b) {
    u64 r;
    asm("add.rn.f32x2 %0, %1, %2;" : "=l"(r) : "l"(a), "l"(b));
    return r;
}
__device__ __forceinline__ u64 f2fma(u64 a, u64 b, u64 c) {
    u64 r;
    asm("fma.rn.f32x2 %0, %1, %2, %3;" : "=l"(r) : "l"(a), "l"(b), "l"(c));
    return r;
}
__device__ __forceinline__ void cp16(unsigned int saddr, const void* gaddr) {
    asm volatile("cp.async.cg.shared.global [%0], [%1], 16;"
                 :: "r"(saddr), "l"(gaddr));
}
__device__ __forceinline__ unsigned int smem_u32(const void* p) {
    return (unsigned int)__cvta_generic_to_shared(p);
}

// ---------------- prep_nn --------------------------------------------------
// Pair record, 14 slots of f32x2 (28 floats, 112B):
//  q0-2: n, q3: v0.n, q4-6: C01, q7: e01, q8-10: C12, q11: e12,
//  q12: E = e01+e12+e20, q13: pad.   (C20 = -(C01+C12) by identity.)
__global__ void __launch_bounds__(256) prep_nn_kernel(const float* __restrict__ sr,
                                                      const float* __restrict__ hv,
                                                      const float* __restrict__ fn,
                                                      const int*   __restrict__ hf,
                                                      const float* __restrict__ obj,
                                                      float* __restrict__ out) {
    if (blockIdx.x < PREP_BLKS) {
        // ---------------- prep part ----------------
        int f = blockIdx.x * 256 + threadIdx.x;   // 0..4095
        if (f == 0) g_ctr = 0;
        if (f < NGRP) g_gctr[f] = 0;
        g_hits[f] = 0;
        g_hits[f + N_F] = 0;

        int i0 = hf[3 * f + 0], i1 = hf[3 * f + 1], i2 = hf[3 * f + 2];
        float nx = fn[3 * f + 0], ny = fn[3 * f + 1], nz = fn[3 * f + 2];
        float v0x = hv[3 * i0 + 0], v0y = hv[3 * i0 + 1], v0z = hv[3 * i0 + 2];
        float v1x = hv[3 * i1 + 0], v1y = hv[3 * i1 + 1], v1z = hv[3 * i1 + 2];
        float v2x = hv[3 * i2 + 0], v2y = hv[3 * i2 + 1], v2z = hv[3 * i2 + 2];

        float vals[14];
        vals[0] = nx; vals[1] = ny; vals[2] = nz;
        vals[3] = v0x * nx + v0y * ny + v0z * nz;

        float eA, eB, eC;
        {   // edge 01
            float wx = v1x - v0x, wy = v1y - v0y, wz = v1z - v0z;
            float cx = ny * wz - nz * wy, cy = nz * wx - nx * wz, cz = nx * wy - ny * wx;
            vals[4] = cx; vals[5] = cy; vals[6] = cz;
            eA = -(v0x * cx + v0y * cy + v0z * cz);
            vals[7] = eA;
        }
        {   // edge 12
            float wx = v2x - v1x, wy = v2y - v1y, wz = v2z - v1z;
            float cx = ny * wz - nz * wy, cy = nz * wx - nx * wz, cz = nx * wy - ny * wx;
            vals[8] = cx; vals[9] = cy; vals[10] = cz;
            eB = -(v1x * cx + v1y * cy + v1z * cz);
            vals[11] = eB;
        }
        {   // edge 20 (only its offset is needed)
            float wx = v0x - v2x, wy = v0y - v2y, wz = v0z - v2z;
            float cx = ny * wz - nz * wy, cy = nz * wx - nx * wz, cz = nx * wy - ny * wx;
            eC = -(v2x * cx + v2y * cy + v2z * cz);
        }
        vals[12] = eA + eB + eC;
        vals[13] = 0.0f;

        int p = f >> 1, h = f & 1;
        float* o = reinterpret_cast<float*>(g_face4) + p * 28 + h;
#pragma unroll
        for (int q = 0; q < 14; q++) o[2 * q] = vals[q];
        return;
    }

    // ---------------- nn part (2 points per warp; reads raw sr) ------------
    int wid = threadIdx.x >> 5, lane = threadIdx.x & 31;
    int pbase = (blockIdx.x - PREP_BLKS) * 16 + wid * 2;

    float ox0 = obj[3 * (pbase + 0) + 0], oy0 = obj[3 * (pbase + 0) + 1], oz0 = obj[3 * (pbase + 0) + 2];
    float ox1 = obj[3 * (pbase + 1) + 0], oy1 = obj[3 * (pbase + 1) + 1], oz1 = obj[3 * (pbase + 1) + 2];
    float o20 = ox0 * ox0 + oy0 * oy0 + oz0 * oz0;
    float o21 = ox1 * ox1 + oy1 * oy1 + oz1 * oz1;

    float b0 = 3.402823466e38f, b1 = b0;
    int j0 = 0, j1 = 0;

#pragma unroll 4
    for (int j = lane; j < N_SR; j += 32) {
        float sx = __ldg(&sr[3 * j + 0]);
        float sy = __ldg(&sr[3 * j + 1]);
        float sz = __ldg(&sr[3 * j + 2]);
        float s2 = sx * sx + sy * sy + sz * sz;
        float d0 = fmaf(-2.0f, ox0 * sx + fmaf(oy0, sy, oz0 * sz), o20 + s2);
        float d1 = fmaf(-2.0f, ox1 * sx + fmaf(oy1, sy, oz1 * sz), o21 + s2);
        if (d0 < b0) { b0 = d0; j0 = j; }
        if (d1 < b1) { b1 = d1; j1 = j; }
    }
#pragma unroll
    for (int off = 16; off; off >>= 1) {
        float t; int tj;
        t = __shfl_down_sync(~0u, b0, off); tj = __shfl_down_sync(~0u, j0, off);
        if (t < b0 || (t == b0 && tj < j0)) { b0 = t; j0 = tj; }
        t = __shfl_down_sync(~0u, b1, off); tj = __shfl_down_sync(~0u, j1, off);
        if (t < b1 || (t == b1 && tj < j1)) { b1 = t; j1 = tj; }
    }

    if (lane == 0) {
        float obx[2] = {ox0, ox1};
        float oby[2] = {oy0, oy1};
        float obz[2] = {oz0, oz1};
        float bb[2] = {b0, b1};
        int   jj[2] = {j0, j1};
#pragma unroll
        for (int k = 0; k < 2; k++) {
            float sx = sr[3 * jj[k] + 0], sy = sr[3 * jj[k] + 1], sz = sr[3 * jj[k] + 2];
            float Dx = sx - obx[k], Dy = sy - oby[k], Dz = sz - obz[k];
            g_D4[pbase + k] = make_float4(Dx, Dy, Dz, Dx * Dx + Dy * Dy + Dz * Dz);
            float nnd = sqrtf(fmaxf(bb[k], 0.0f));
            out[1 + pbase + k] = 2.0f / (1.0f + expf(100.0f * nnd));
        }
    }
}

// ---------------- hits: parity + reductions --------------------------------
// Block = (group, slice): 32 points (lane=point) x 256 face-pairs.
__global__ void __launch_bounds__(256, 5) hits_kernel(const float* __restrict__ obj,
                                                      float* __restrict__ out) {
    __shared__ __align__(16) char s_face[2][TILE_BYTES];   // 2 x 14 KB
    __shared__ int    s_cnt[8][32];
    __shared__ int    s_glast, s_last;
    __shared__ float  s_red[256];

    int tid = threadIdx.x;
    int wid = tid >> 5, lane = tid & 31;
    int grp = blockIdx.x >> 3, fq = blockIdx.x & 7;
    int pt  = grp * 32 + lane;

    float ox = obj[3 * pt + 0], oy = obj[3 * pt + 1], oz = obj[3 * pt + 2];
    float4 D = __ldg(&g_D4[pt]);

    u64 OX = pk(ox, ox), OY = pk(oy, oy), OZ = pk(oz, oz);
    u64 DX = pk(D.x, D.x), DY = pk(D.y, D.y), DZ = pk(D.z, D.z);
    u64 NEG1 = pk(-1.0f, -1.0f);
    u64 MEPS = pk(-EPSF, -EPSF);
    const unsigned int EPS_BITS = __float_as_uint(EPSF);
    const unsigned int SGN = 0x80000000u;

    const char* gfb = reinterpret_cast<const char*>(g_face4)
                      + (size_t)fq * PAIRS_PER_FQ * REC_U * 16;

    // stage tile 0
    {
        unsigned int sb = smem_u32(&s_face[0][0]);
#pragma unroll
        for (int k = 0; k < 4; k++) {
            int idx = tid + k * 256;
            if (idx < CHUNKS) cp16(sb + idx * 16, gfb + idx * 16);
        }
        asm volatile("cp.async.commit_group;" ::: "memory");
    }

    int cnt = 0;

    for (int t = 0; t < NTILE_FQ; t++) {
        if (t + 1 < NTILE_FQ) {
            unsigned int sb = smem_u32(&s_face[(t + 1) & 1][0]);
            const char* gsrc = gfb + (t + 1) * TILE_BYTES;
#pragma unroll
            for (int k = 0; k < 4; k++) {
                int idx = tid + k * 256;
                if (idx < CHUNKS) cp16(sb + idx * 16, gsrc + idx * 16);
            }
            asm volatile("cp.async.commit_group;" ::: "memory");
            asm volatile("cp.async.wait_group 1;" ::: "memory");
        } else {
            asm volatile("cp.async.wait_group 0;" ::: "memory");
        }
        __syncthreads();

        const ulonglong2* up = reinterpret_cast<const ulonglong2*>(
            &s_face[t & 1][0]) + (wid * (TILE_P / 8)) * REC_U;

#pragma unroll 4
        for (int lp = 0; lp < TILE_P / 8; lp++, up += REC_U) {
            ulonglong2 t0 = up[0];   // nx | ny
            ulonglong2 t1 = up[1];   // nz | v0n
            ulonglong2 t2 = up[2];   // CAx | CAy
            ulonglong2 t3 = up[3];   // CAz | eA
            ulonglong2 t4 = up[4];   // CBx | CBy
            ulonglong2 t5 = up[5];   // CBz | eB
            u64 Ev = up[6].x;        // E (f32x2)

            // normal block
            u64 no   = f2fma(t0.x, OX, f2fma(t0.y, OY, f2mul(t1.x, OZ)));
            u64 num  = f2fma(no, NEG1, t1.y);      // v0n - n.o
            u64 den  = f2fma(t0.x, DX, f2fma(t0.y, DY, f2mul(t1.x, DZ)));

            // edge A
            u64 ba = f2fma(t2.x, OX, f2fma(t2.y, OY, f2fma(t3.x, OZ, t3.y)));
            u64 da = f2fma(t2.x, DX, f2fma(t2.y, DY, f2mul(t3.x, DZ)));
            u64 qa = f2fma(ba, den, f2mul(num, da));

            // edge B
            u64 bb_ = f2fma(t4.x, OX, f2fma(t4.y, OY, f2fma(t5.x, OZ, t5.y)));
            u64 db  = f2fma(t4.x, DX, f2fma(t4.y, DY, f2mul(t5.x, DZ)));
            u64 qb  = f2fma(bb_, den, f2mul(num, db));

            // edge C (negated) by identity: C20 = -(C01+C12), e-sum E.
            //   qcn = (ba + bb - E)*den + num*(da+db) = -qc
            // sign(qc)==sign(den)  <=>  sign(qcn)==sign(-den)
            u64 sab = f2add(da, db);
            u64 tab = f2add(ba, bb_);
            u64 nbc = f2fma(Ev, NEG1, tab);               // tab - E
            u64 qcn = f2fma(nbc, den, f2mul(num, sab));

            // w = num - EPS*den
            u64 wv = f2fma(MEPS, den, num);

            unsigned int qa0, qa1, qb0, qb1, qc0, qc1, w0, w1, d0, d1;
            upku(qa, qa0, qa1);
            upku(qb, qb0, qb1);
            upku(qcn, qc0, qc1);
            upku(wv, w0, w1);
            upku(den, d0, d1);

            unsigned int dn0 = d0 ^ SGN, dn1 = d1 ^ SGN;
            unsigned int x0 = ((qa0 ^ d0) | (qb0 ^ d0)) | ((qc0 ^ dn0) | (w0 ^ d0));
            unsigned int x1 = ((qa1 ^ d1) | (qb1 ^ d1)) | ((qc1 ^ dn1) | (w1 ^ d1));
            cnt += (int)(((int)x0 >= 0) & ((d0 & 0x7fffffffu) > EPS_BITS));
            cnt += (int)(((int)x1 >= 0) & ((d1 & 0x7fffffffu) > EPS_BITS));
        }
        __syncthreads();
    }

    s_cnt[wid][lane] = cnt;
    __syncthreads();

    // warp 0 accumulates this block's per-point counts into gmem (int = exact)
    if (wid == 0) {
        int tot = 0;
#pragma unroll
        for (int k = 0; k < 8; k++) tot += s_cnt[k][lane];
        atomicAdd(&g_hits[pt], tot);
    }

    // group completion
    if (tid == 0) {
        __threadfence();
        unsigned int a = atomicAdd(&g_gctr[grp], 1u);
        s_glast = (a == NFQ - 1) ? 1 : 0;
        s_last = 0;
    }
    __syncthreads();

    if (s_glast) {
        if (wid == 0) {
            int tot;
            asm volatile("ld.global.cg.s32 %0, [%1];" : "=r"(tot)
                         : "l"(&g_hits[pt]));
            float dw;
            asm volatile("ld.global.cg.f32 %0, [%1];" : "=f"(dw)
                         : "l"(reinterpret_cast<const float*>(&g_D4[pt]) + 3));
            float pen = (tot & 1) ? dw : 0.0f;
#pragma unroll
            for (int off = 16; off; off >>= 1)
                pen += __shfl_down_sync(~0u, pen, off);
            if (lane == 0) {
                g_part[grp] = pen;
                __threadfence();
                unsigned int a = atomicAdd(&g_ctr, 1u);
                if (a == NGRP - 1) s_last = 1;
            }
        }
        __syncthreads();

        if (s_last) {
            float v;
            asm volatile("ld.global.cg.f32 %0, [%1];" : "=f"(v)
                         : "l"(&g_part[tid]));
            s_red[tid] = v;
            __syncthreads();
#pragma unroll
            for (int off = 128; off; off >>= 1) {
                if (tid < off) s_red[tid] += s_red[tid + off];
                __syncthreads();
            }
            if (tid == 0) out[0] = sqrtf(s_red[0] + 1e-12f);
        }
    }
}

// ---------------- launch ---------------------------------------------------
extern "C" void kernel_launch(void* const* d_in, const int* in_sizes, int n_in,
                              void* d_out, int out_size) {
    const float* obj = (const float*)d_in[0];
    const float* sr  = (const float*)d_in[1];
    const float* hv  = (const float*)d_in[2];
    const float* fn  = (const float*)d_in[3];
    const int*   hf  = (const int*)d_in[4];
    float* out = (float*)d_out;

    prep_nn_kernel<<<PREP_BLKS + NN_BLKS, 256>>>(sr, hv, fn, hf, obj, out);
    hits_kernel<<<NGRP * NFQ, 256>>>(obj, out);
}

// round 14
// speedup vs baseline: 1.2967x; 1.0005x over previous
#include <cuda_runtime.h>

// SR_Loss: NN(obj->sr) + ray-triangle parity interior test + reductions.
// obj 8192x3, sr 4096x3, verts 4100x3, normals 4096x3, faces 4096x3.
// Output: [pen_dist, cmap(8192)] = 8193 f32.
//
// 2 kernels:
//  prep_nn : blocks 0-15 build face constants (28 f/pair, edge-C eliminated)
//            + zero counters; blocks 16-527 do NN (2 points/warp) with sr
//            staged in smem (conflict-free LDS, 3 wf/iter vs 9 for LDG).
//  hits    : 2048 blocks = 256 point-groups x 8 face-slices; whole 28KB slice
//            staged once into smem (1 sync); f32x2 packed sign tests; int
//            atomics for hit counts; group-last pen partial; global-last
//            reduces pen_dist.

#define N_OBJ  8192
#define N_SR   4096
#define N_F    4096
#define NPAIR  (N_F / 2)          // 2048
#define EPSF   1e-8f
#define NGRP   (N_OBJ / 32)       // 256 point groups
#define NFQ    8                  // face slices per group
#define PAIRS_PER_FQ (NPAIR / NFQ) // 256

#define REC_U      7                          // ulonglong2 per pair record
#define SLICE_BYTES (PAIRS_PER_FQ * REC_U * 16)  // 28672
#define SLICE_CHUNKS (SLICE_BYTES / 16)          // 1792

#define PREP_BLKS  16
#define NN_BLKS    512

typedef unsigned long long u64;

// ---------------- scratch (device globals; no allocation allowed) ----------
__device__ float4 g_face4[NPAIR * REC_U];   // pair-interleaved records (28 f/pair)
__device__ float4 g_D4[N_OBJ];              // D = trg - o, .w = |D|^2
__device__ int    g_hits[N_OBJ];            // accumulated hit counts
__device__ float  g_part[NGRP];             // per-group pen partials
__device__ unsigned int g_gctr[NGRP];       // per-group arrival counters
__device__ unsigned int g_ctr;              // global arrival counter

// ---------------- f32x2 packed helpers (sm_103a) ---------------------------
__device__ __forceinline__ u64 pk(float lo, float hi) {
    u64 r;
    asm("mov.b64 %0, {%1, %2};" : "=l"(r)
        : "r"(__float_as_uint(lo)), "r"(__float_as_uint(hi)));
    return r;
}
__device__ __forceinline__ void upku(u64 v, unsigned int& lo, unsigned int& hi) {
    asm("mov.b64 {%0, %1}, %2;" : "=r"(lo), "=r"(hi) : "l"(v));
}
__device__ __forceinline__ u64 f2mul(u64 a, u64 b) {
    u64 r;
    asm("mul.rn.f32x2 %0, %1, %2;" : "=l"(r) : "l"(a), "l"(b));
    return r;
}
__device__ __forceinline__ u64 f2add(u64 a, u64 b) {
    u64 r;
    asm("add.rn.f32x2 %0, %1, %2;" : "=l"(r) : "l"(a), "l"(b));
    return r;
}
__device__ __forceinline__ u64 f2fma(u64 a, u64 b, u64 c) {
    u64 r;
    asm("fma.rn.f32x2 %0, %1, %2, %3;" : "=l"(r) : "l"(a), "l"(b), "l"(c));
    return r;
}
__device__ __forceinline__ void cp16(unsigned int saddr, const void* gaddr) {
    asm volatile("cp.async.cg.shared.global [%0], [%1], 16;"
                 :: "r"(saddr), "l"(gaddr));
}
__device__ __forceinline__ unsigned int smem_u32(const void* p) {
    return (unsigned int)__cvta_generic_to_shared(p);
}

// ---------------- prep_nn --------------------------------------------------
// Pair record, 14 slots of f32x2 (28 floats, 112B):
//  q0-2: n, q3: v0.n, q4-6: C01, q7: e01, q8-10: C12, q11: e12,
//  q12: E = e01+e12+e20, q13: pad.   (C20 = -(C01+C12) by identity.)
__global__ void __launch_bounds__(256) prep_nn_kernel(const float* __restrict__ sr,
                                                      const float* __restrict__ hv,
                                                      const float* __restrict__ fn,
                                                      const int*   __restrict__ hf,
                                                      const float* __restrict__ obj,
                                                      float* __restrict__ out) {
    __shared__ float s_flat[N_SR * 3];   // 48 KB staged copy of sr

    if (blockIdx.x < PREP_BLKS) {
        // ---------------- prep part ----------------
        int f = blockIdx.x * 256 + threadIdx.x;   // 0..4095
        if (f == 0) g_ctr = 0;
        if (f < NGRP) g_gctr[f] = 0;
        g_hits[f] = 0;
        g_hits[f + N_F] = 0;

        int i0 = hf[3 * f + 0], i1 = hf[3 * f + 1], i2 = hf[3 * f + 2];
        float nx = fn[3 * f + 0], ny = fn[3 * f + 1], nz = fn[3 * f + 2];
        float v0x = hv[3 * i0 + 0], v0y = hv[3 * i0 + 1], v0z = hv[3 * i0 + 2];
        float v1x = hv[3 * i1 + 0], v1y = hv[3 * i1 + 1], v1z = hv[3 * i1 + 2];
        float v2x = hv[3 * i2 + 0], v2y = hv[3 * i2 + 1], v2z = hv[3 * i2 + 2];

        float vals[14];
        vals[0] = nx; vals[1] = ny; vals[2] = nz;
        vals[3] = v0x * nx + v0y * ny + v0z * nz;

        float eA, eB, eC;
        {   // edge 01
            float wx = v1x - v0x, wy = v1y - v0y, wz = v1z - v0z;
            float cx = ny * wz - nz * wy, cy = nz * wx - nx * wz, cz = nx * wy - ny * wx;
            vals[4] = cx; vals[5] = cy; vals[6] = cz;
            eA = -(v0x * cx + v0y * cy + v0z * cz);
            vals[7] = eA;
        }
        {   // edge 12
            float wx = v2x - v1x, wy = v2y - v1y, wz = v2z - v1z;
            float cx = ny * wz - nz * wy, cy = nz * wx - nx * wz, cz = nx * wy - ny * wx;
            vals[8] = cx; vals[9] = cy; vals[10] = cz;
            eB = -(v1x * cx + v1y * cy + v1z * cz);
            vals[11] = eB;
        }
        {   // edge 20 (only its offset is needed)
            float wx = v0x - v2x, wy = v0y - v2y, wz = v0z - v2z;
            float cx = ny * wz - nz * wy, cy = nz * wx - nx * wz, cz = nx * wy - ny * wx;
            eC = -(v2x * cx + v2y * cy + v2z * cz);
        }
        vals[12] = eA + eB + eC;
        vals[13] = 0.0f;

        int p = f >> 1, h = f & 1;
        float* o = reinterpret_cast<float*>(g_face4) + p * 28 + h;
#pragma unroll
        for (int q = 0; q < 14; q++) o[2 * q] = vals[q];
        return;
    }

    // ---------------- nn part (2 points per warp; sr staged in smem) -------
    int tid = threadIdx.x;
    int wid = tid >> 5, lane = tid & 31;
    int pbase = (blockIdx.x - PREP_BLKS) * 16 + wid * 2;

    // stage sr: 12288 floats = 3072 float4, 12 per thread, coalesced
    {
        const float4* s4 = reinterpret_cast<const float4*>(sr);
        float4* d4 = reinterpret_cast<float4*>(s_flat);
#pragma unroll
        for (int k = 0; k < 12; k++)
            d4[tid + k * 256] = __ldg(&s4[tid + k * 256]);
    }

    float ox0 = obj[3 * (pbase + 0) + 0], oy0 = obj[3 * (pbase + 0) + 1], oz0 = obj[3 * (pbase + 0) + 2];
    float ox1 = obj[3 * (pbase + 1) + 0], oy1 = obj[3 * (pbase + 1) + 1], oz1 = obj[3 * (pbase + 1) + 2];
    float o20 = ox0 * ox0 + oy0 * oy0 + oz0 * oz0;
    float o21 = ox1 * ox1 + oy1 * oy1 + oz1 * oz1;

    __syncthreads();

    float b0 = 3.402823466e38f, b1 = b0;
    int j0 = 0, j1 = 0;

#pragma unroll 4
    for (int j = lane; j < N_SR; j += 32) {
        // lane stride = 3 words, coprime to 32 banks -> conflict-free LDS
        float sx = s_flat[3 * j + 0];
        float sy = s_flat[3 * j + 1];
        float sz = s_flat[3 * j + 2];
        float s2 = sx * sx + sy * sy + sz * sz;
        float d0 = fmaf(-2.0f, ox0 * sx + fmaf(oy0, sy, oz0 * sz), o20 + s2);
        float d1 = fmaf(-2.0f, ox1 * sx + fmaf(oy1, sy, oz1 * sz), o21 + s2);
        if (d0 < b0) { b0 = d0; j0 = j; }
        if (d1 < b1) { b1 = d1; j1 = j; }
    }
#pragma unroll
    for (int off = 16; off; off >>= 1) {
        float t; int tj;
        t = __shfl_down_sync(~0u, b0, off); tj = __shfl_down_sync(~0u, j0, off);
        if (t < b0 || (t == b0 && tj < j0)) { b0 = t; j0 = tj; }
        t = __shfl_down_sync(~0u, b1, off); tj = __shfl_down_sync(~0u, j1, off);
        if (t < b1 || (t == b1 && tj < j1)) { b1 = t; j1 = tj; }
    }

    if (lane == 0) {
        float obx[2] = {ox0, ox1};
        float oby[2] = {oy0, oy1};
        float obz[2] = {oz0, oz1};
        float bb[2] = {b0, b1};
        int   jj[2] = {j0, j1};
#pragma unroll
        for (int k = 0; k < 2; k++) {
            float sx = s_flat[3 * jj[k] + 0], sy = s_flat[3 * jj[k] + 1], sz = s_flat[3 * jj[k] + 2];
            float Dx = sx - obx[k], Dy = sy - oby[k], Dz = sz - obz[k];
            g_D4[pbase + k] = make_float4(Dx, Dy, Dz, Dx * Dx + Dy * Dy + Dz * Dz);
            float nnd = sqrtf(fmaxf(bb[k], 0.0f));
            out[1 + pbase + k] = 2.0f / (1.0f + expf(100.0f * nnd));
        }
    }
}

// ---------------- hits: parity + reductions --------------------------------
// Block = (group, slice): 32 points (lane=point) x 256 face-pairs.
// Whole slice (28 KB) staged once; single __syncthreads before compute.
__global__ void __launch_bounds__(256, 5) hits_kernel(const float* __restrict__ obj,
                                                      float* __restrict__ out) {
    __shared__ __align__(16) char s_face[SLICE_BYTES];   // 28 KB
    __shared__ int    s_cnt[8][32];
    __shared__ int    s_glast, s_last;
    __shared__ float  s_red[256];

    int tid = threadIdx.x;
    int wid = tid >> 5, lane = tid & 31;
    int grp = blockIdx.x >> 3, fq = blockIdx.x & 7;
    int pt  = grp * 32 + lane;

    // stage whole slice: 1792 chunks, 7 per thread
    {
        const char* gfb = reinterpret_cast<const char*>(g_face4)
                          + (size_t)fq * SLICE_BYTES;
        unsigned int sb = smem_u32(&s_face[0]);
#pragma unroll
        for (int k = 0; k < 7; k++) {
            int idx = tid + k * 256;
            cp16(sb + idx * 16, gfb + idx * 16);
        }
        asm volatile("cp.async.commit_group;" ::: "memory");
    }

    float ox = obj[3 * pt + 0], oy = obj[3 * pt + 1], oz = obj[3 * pt + 2];
    float4 D = __ldg(&g_D4[pt]);

    u64 OX = pk(ox, ox), OY = pk(oy, oy), OZ = pk(oz, oz);
    u64 DX = pk(D.x, D.x), DY = pk(D.y, D.y), DZ = pk(D.z, D.z);
    u64 NEG1 = pk(-1.0f, -1.0f);
    u64 MEPS = pk(-EPSF, -EPSF);
    const unsigned int EPS_BITS = __float_as_uint(EPSF);
    const unsigned int SGN = 0x80000000u;

    asm volatile("cp.async.wait_group 0;" ::: "memory");
    __syncthreads();

    int cnt = 0;
    const ulonglong2* up = reinterpret_cast<const ulonglong2*>(&s_face[0])
                           + (wid * (PAIRS_PER_FQ / 8)) * REC_U;

#pragma unroll 4
    for (int lp = 0; lp < PAIRS_PER_FQ / 8; lp++, up += REC_U) {
        ulonglong2 t0 = up[0];   // nx | ny
        ulonglong2 t1 = up[1];   // nz | v0n
        ulonglong2 t2 = up[2];   // CAx | CAy
        ulonglong2 t3 = up[3];   // CAz | eA
        ulonglong2 t4 = up[4];   // CBx | CBy
        ulonglong2 t5 = up[5];   // CBz | eB
        u64 Ev = up[6].x;        // E (f32x2)

        // normal block
        u64 no   = f2fma(t0.x, OX, f2fma(t0.y, OY, f2mul(t1.x, OZ)));
        u64 num  = f2fma(no, NEG1, t1.y);      // v0n - n.o
        u64 den  = f2fma(t0.x, DX, f2fma(t0.y, DY, f2mul(t1.x, DZ)));

        // edge A
        u64 ba = f2fma(t2.x, OX, f2fma(t2.y, OY, f2fma(t3.x, OZ, t3.y)));
        u64 da = f2fma(t2.x, DX, f2fma(t2.y, DY, f2mul(t3.x, DZ)));
        u64 qa = f2fma(ba, den, f2mul(num, da));

        // edge B
        u64 bb_ = f2fma(t4.x, OX, f2fma(t4.y, OY, f2fma(t5.x, OZ, t5.y)));
        u64 db  = f2fma(t4.x, DX, f2fma(t4.y, DY, f2mul(t5.x, DZ)));
        u64 qb  = f2fma(bb_, den, f2mul(num, db));

        // edge C (negated) by identity: C20 = -(C01+C12), e-sum E.
        //   qcn = (ba + bb - E)*den + num*(da+db) = -qc
        // sign(qc)==sign(den)  <=>  sign(qcn)==sign(-den)
        u64 sab = f2add(da, db);
        u64 tab = f2add(ba, bb_);
        u64 nbc = f2fma(Ev, NEG1, tab);               // tab - E
        u64 qcn = f2fma(nbc, den, f2mul(num, sab));

        // w = num - EPS*den
        u64 wv = f2fma(MEPS, den, num);

        unsigned int qa0, qa1, qb0, qb1, qc0, qc1, w0, w1, d0, d1;
        upku(qa, qa0, qa1);
        upku(qb, qb0, qb1);
        upku(qcn, qc0, qc1);
        upku(wv, w0, w1);
        upku(den, d0, d1);

        unsigned int dn0 = d0 ^ SGN, dn1 = d1 ^ SGN;
        unsigned int x0 = ((qa0 ^ d0) | (qb0 ^ d0)) | ((qc0 ^ dn0) | (w0 ^ d0));
        unsigned int x1 = ((qa1 ^ d1) | (qb1 ^ d1)) | ((qc1 ^ dn1) | (w1 ^ d1));
        cnt += (int)(((int)x0 >= 0) & ((d0 & 0x7fffffffu) > EPS_BITS));
        cnt += (int)(((int)x1 >= 0) & ((d1 & 0x7fffffffu) > EPS_BITS));
    }

    s_cnt[wid][lane] = cnt;
    __syncthreads();

    // warp 0 accumulates this block's per-point counts into gmem (int = exact)
    if (wid == 0) {
        int tot = 0;
#pragma unroll
        for (int k = 0; k < 8; k++) tot += s_cnt[k][lane];
        atomicAdd(&g_hits[pt], tot);
    }

    // group completion
    if (tid == 0) {
        __threadfence();
        unsigned int a = atomicAdd(&g_gctr[grp], 1u);
        s_glast = (a == NFQ - 1) ? 1 : 0;
        s_last = 0;
    }
    __syncthreads();

    if (s_glast) {
        if (wid == 0) {
            int tot;
            asm volatile("ld.global.cg.s32 %0, [%1];" : "=r"(tot)
                         : "l"(&g_hits[pt]));
            float dw;
            asm volatile("ld.global.cg.f32 %0, [%1];" : "=f"(dw)
                         : "l"(reinterpret_cast<const float*>(&g_D4[pt]) + 3));
            float pen = (tot & 1) ? dw : 0.0f;
#pragma unroll
            for (int off = 16; off; off >>= 1)
                pen += __shfl_down_sync(~0u, pen, off);
            if (lane == 0) {
                g_part[grp] = pen;
                __threadfence();
                unsigned int a = atomicAdd(&g_ctr, 1u);
                if (a == NGRP - 1) s_last = 1;
            }
        }
        __syncthreads();

        if (s_last) {
            float v;
            asm volatile("ld.global.cg.f32 %0, [%1];" : "=f"(v)
                         : "l"(&g_part[tid]));
            s_red[tid] = v;
            __syncthreads();
#pragma unroll
            for (int off = 128; off; off >>= 1) {
                if (tid < off) s_red[tid] += s_red[tid + off];
                __syncthreads();
            }
            if (tid == 0) out[0] = sqrtf(s_red[0] + 1e-12f);
        }
    }
}

// ---------------- launch ---------------------------------------------------
extern "C" void kernel_launch(void* const* d_in, const int* in_sizes, int n_in,
                              void* d_out, int out_size) {
    const float* obj = (const float*)d_in[0];
    const float* sr  = (const float*)d_in[1];
    const float* hv  = (const float*)d_in[2];
    const float* fn  = (const float*)d_in[3];
    const int*   hf  = (const int*)d_in[4];
    float* out = (float*)d_out;

    prep_nn_kernel<<<PREP_BLKS + NN_BLKS, 256>>>(sr, hv, fn, hf, obj, out);
    hits_kernel<<<NGRP * NFQ, 256>>>(obj, out);
}

// round 15
// speedup vs baseline: 1.3115x; 1.0114x over previous
#include <cuda_runtime.h>

// SR_Loss: NN(obj->sr) + ray-triangle parity interior test + reductions.
// obj 8192x3, sr 4096x3, verts 4100x3, normals 4096x3, faces 4096x3.
// Output: [pen_dist, cmap(8192)] = 8193 f32.
//
// 3 kernels:
//  sr4     : build g_sr4 float4 {x,y,z,|s|^2} (removes prep->nn dependency).
//  prep_nn : blocks 0-15 face constants (28 f/pair, edge-C eliminated) +
//            zero counters; blocks 16-527 NN (2 pts/warp, float4 g_sr4 loop).
//  hits    : 2048 blocks = 256 point-groups x 8 face-slices; 28KB smem slice,
//            f32x2 packed sign tests; int atomics; group-last pen partial;
//            global-last reduces pen_dist.

#define N_OBJ  8192
#define N_SR   4096
#define N_F    4096
#define NPAIR  (N_F / 2)          // 2048
#define EPSF   1e-8f
#define NGRP   (N_OBJ / 32)       // 256 point groups
#define NFQ    8                  // face slices per group
#define PAIRS_PER_FQ (NPAIR / NFQ) // 256

#define REC_U      7                          // ulonglong2 per pair record
#define SLICE_BYTES (PAIRS_PER_FQ * REC_U * 16)  // 28672
#define SLICE_CHUNKS (SLICE_BYTES / 16)          // 1792

#define PREP_BLKS  16
#define NN_BLKS    512

typedef unsigned long long u64;

// ---------------- scratch (device globals; no allocation allowed) ----------
__device__ float4 g_sr4[N_SR];              // sr point + |s|^2
__device__ float4 g_face4[NPAIR * REC_U];   // pair-interleaved records (28 f/pair)
__device__ float4 g_D4[N_OBJ];              // D = trg - o, .w = |D|^2
__device__ int    g_hits[N_OBJ];            // accumulated hit counts
__device__ float  g_part[NGRP];             // per-group pen partials
__device__ unsigned int g_gctr[NGRP];       // per-group arrival counters
__device__ unsigned int g_ctr;              // global arrival counter

// ---------------- f32x2 packed helpers (sm_103a) ---------------------------
__device__ __forceinline__ u64 pk(float lo, float hi) {
    u64 r;
    asm("mov.b64 %0, {%1, %2};" : "=l"(r)
        : "r"(__float_as_uint(lo)), "r"(__float_as_uint(hi)));
    return r;
}
__device__ __forceinline__ void upku(u64 v, unsigned int& lo, unsigned int& hi) {
    asm("mov.b64 {%0, %1}, %2;" : "=r"(lo), "=r"(hi) : "l"(v));
}
__device__ __forceinline__ u64 f2mul(u64 a, u64 b) {
    u64 r;
    asm("mul.rn.f32x2 %0, %1, %2;" : "=l"(r) : "l"(a), "l"(b));
    return r;
}
__device__ __forceinline__ u64 f2add(u64 a, u64 b) {
    u64 r;
    asm("add.rn.f32x2 %0, %1, %2;" : "=l"(r) : "l"(a), "l"(b));
    return r;
}
__device__ __forceinline__ u64 f2fma(u64 a, u64 b, u64 c) {
    u64 r;
    asm("fma.rn.f32x2 %0, %1, %2, %3;" : "=l"(r) : "l"(a), "l"(b), "l"(c));
    return r;
}
__device__ __forceinline__ void cp16(unsigned int saddr, const void* gaddr) {
    asm volatile("cp.async.cg.shared.global [%0], [%1], 16;"
                 :: "r"(saddr), "l"(gaddr));
}
__device__ __forceinline__ unsigned int smem_u32(const void* p) {
    return (unsigned int)__cvta_generic_to_shared(p);
}

// ---------------- sr4: build packed sr table --------------------------------
__global__ void __launch_bounds__(256) sr4_kernel(const float* __restrict__ sr) {
    int j = blockIdx.x * 256 + threadIdx.x;   // 0..4095
    float sx = sr[3 * j + 0], sy = sr[3 * j + 1], sz = sr[3 * j + 2];
    g_sr4[j] = make_float4(sx, sy, sz, sx * sx + sy * sy + sz * sz);
}

// ---------------- prep_nn --------------------------------------------------
// Pair record, 14 slots of f32x2 (28 floats, 112B):
//  q0-2: n, q3: v0.n, q4-6: C01, q7: e01, q8-10: C12, q11: e12,
//  q12: E = e01+e12+e20, q13: pad.   (C20 = -(C01+C12) by identity.)
__global__ void __launch_bounds__(256) prep_nn_kernel(const float* __restrict__ hv,
                                                      const float* __restrict__ fn,
                                                      const int*   __restrict__ hf,
                                                      const float* __restrict__ obj,
                                                      float* __restrict__ out) {
    if (blockIdx.x < PREP_BLKS) {
        // ---------------- prep part ----------------
        int f = blockIdx.x * 256 + threadIdx.x;   // 0..4095
        if (f == 0) g_ctr = 0;
        if (f < NGRP) g_gctr[f] = 0;
        g_hits[f] = 0;
        g_hits[f + N_F] = 0;

        int i0 = hf[3 * f + 0], i1 = hf[3 * f + 1], i2 = hf[3 * f + 2];
        float nx = fn[3 * f + 0], ny = fn[3 * f + 1], nz = fn[3 * f + 2];
        float v0x = hv[3 * i0 + 0], v0y = hv[3 * i0 + 1], v0z = hv[3 * i0 + 2];
        float v1x = hv[3 * i1 + 0], v1y = hv[3 * i1 + 1], v1z = hv[3 * i1 + 2];
        float v2x = hv[3 * i2 + 0], v2y = hv[3 * i2 + 1], v2z = hv[3 * i2 + 2];

        float vals[14];
        vals[0] = nx; vals[1] = ny; vals[2] = nz;
        vals[3] = v0x * nx + v0y * ny + v0z * nz;

        float eA, eB, eC;
        {   // edge 01
            float wx = v1x - v0x, wy = v1y - v0y, wz = v1z - v0z;
            float cx = ny * wz - nz * wy, cy = nz * wx - nx * wz, cz = nx * wy - ny * wx;
            vals[4] = cx; vals[5] = cy; vals[6] = cz;
            eA = -(v0x * cx + v0y * cy + v0z * cz);
            vals[7] = eA;
        }
        {   // edge 12
            float wx = v2x - v1x, wy = v2y - v1y, wz = v2z - v1z;
            float cx = ny * wz - nz * wy, cy = nz * wx - nx * wz, cz = nx * wy - ny * wx;
            vals[8] = cx; vals[9] = cy; vals[10] = cz;
            eB = -(v1x * cx + v1y * cy + v1z * cz);
            vals[11] = eB;
        }
        {   // edge 20 (only its offset is needed)
            float wx = v0x - v2x, wy = v0y - v2y, wz = v0z - v2z;
            float cx = ny * wz - nz * wy, cy = nz * wx - nx * wz, cz = nx * wy - ny * wx;
            eC = -(v2x * cx + v2y * cy + v2z * cz);
        }
        vals[12] = eA + eB + eC;
        vals[13] = 0.0f;

        int p = f >> 1, h = f & 1;
        float* o = reinterpret_cast<float*>(g_face4) + p * 28 + h;
#pragma unroll
        for (int q = 0; q < 14; q++) o[2 * q] = vals[q];
        return;
    }

    // ---------------- nn part (2 points per warp; float4 g_sr4 loop) -------
    int wid = threadIdx.x >> 5, lane = threadIdx.x & 31;
    int pbase = (blockIdx.x - PREP_BLKS) * 16 + wid * 2;

    float ox0 = obj[3 * (pbase + 0) + 0], oy0 = obj[3 * (pbase + 0) + 1], oz0 = obj[3 * (pbase + 0) + 2];
    float ox1 = obj[3 * (pbase + 1) + 0], oy1 = obj[3 * (pbase + 1) + 1], oz1 = obj[3 * (pbase + 1) + 2];
    float o20 = ox0 * ox0 + oy0 * oy0 + oz0 * oz0;
    float o21 = ox1 * ox1 + oy1 * oy1 + oz1 * oz1;

    float b0 = 3.402823466e38f, b1 = b0;
    int j0 = 0, j1 = 0;

#pragma unroll 4
    for (int j = lane; j < N_SR; j += 32) {
        float4 s = __ldg(&g_sr4[j]);
        float d0 = fmaf(-2.0f, ox0 * s.x + fmaf(oy0, s.y, oz0 * s.z), o20 + s.w);
        float d1 = fmaf(-2.0f, ox1 * s.x + fmaf(oy1, s.y, oz1 * s.z), o21 + s.w);
        if (d0 < b0) { b0 = d0; j0 = j; }
        if (d1 < b1) { b1 = d1; j1 = j; }
    }
#pragma unroll
    for (int off = 16; off; off >>= 1) {
        float t; int tj;
        t = __shfl_down_sync(~0u, b0, off); tj = __shfl_down_sync(~0u, j0, off);
        if (t < b0 || (t == b0 && tj < j0)) { b0 = t; j0 = tj; }
        t = __shfl_down_sync(~0u, b1, off); tj = __shfl_down_sync(~0u, j1, off);
        if (t < b1 || (t == b1 && tj < j1)) { b1 = t; j1 = tj; }
    }

    if (lane == 0) {
        float obx[2] = {ox0, ox1};
        float oby[2] = {oy0, oy1};
        float obz[2] = {oz0, oz1};
        float bb[2] = {b0, b1};
        int   jj[2] = {j0, j1};
#pragma unroll
        for (int k = 0; k < 2; k++) {
            float4 s = g_sr4[jj[k]];
            float Dx = s.x - obx[k], Dy = s.y - oby[k], Dz = s.z - obz[k];
            g_D4[pbase + k] = make_float4(Dx, Dy, Dz, Dx * Dx + Dy * Dy + Dz * Dz);
            float nnd = sqrtf(fmaxf(bb[k], 0.0f));
            out[1 + pbase + k] = 2.0f / (1.0f + expf(100.0f * nnd));
        }
    }
}

// ---------------- hits: parity + reductions --------------------------------
// Block = (group, slice): 32 points (lane=point) x 256 face-pairs.
// Whole slice (28 KB) staged once; single __syncthreads before compute.
__global__ void __launch_bounds__(256, 5) hits_kernel(const float* __restrict__ obj,
                                                      float* __restrict__ out) {
    __shared__ __align__(16) char s_face[SLICE_BYTES];   // 28 KB
    __shared__ int    s_cnt[8][32];
    __shared__ int    s_glast, s_last;
    __shared__ float  s_red[256];

    int tid = threadIdx.x;
    int wid = tid >> 5, lane = tid & 31;
    int grp = blockIdx.x >> 3, fq = blockIdx.x & 7;
    int pt  = grp * 32 + lane;

    // stage whole slice: 1792 chunks, 7 per thread
    {
        const char* gfb = reinterpret_cast<const char*>(g_face4)
                          + (size_t)fq * SLICE_BYTES;
        unsigned int sb = smem_u32(&s_face[0]);
#pragma unroll
        for (int k = 0; k < 7; k++) {
            int idx = tid + k * 256;
            cp16(sb + idx * 16, gfb + idx * 16);
        }
        asm volatile("cp.async.commit_group;" ::: "memory");
    }

    float ox = obj[3 * pt + 0], oy = obj[3 * pt + 1], oz = obj[3 * pt + 2];
    float4 D = __ldg(&g_D4[pt]);

    u64 OX = pk(ox, ox), OY = pk(oy, oy), OZ = pk(oz, oz);
    u64 DX = pk(D.x, D.x), DY = pk(D.y, D.y), DZ = pk(D.z, D.z);
    u64 NEG1 = pk(-1.0f, -1.0f);
    u64 MEPS = pk(-EPSF, -EPSF);
    const unsigned int EPS_BITS = __float_as_uint(EPSF);
    const unsigned int SGN = 0x80000000u;

    asm volatile("cp.async.wait_group 0;" ::: "memory");
    __syncthreads();

    int cnt = 0;
    const ulonglong2* up = reinterpret_cast<const ulonglong2*>(&s_face[0])
                           + (wid * (PAIRS_PER_FQ / 8)) * REC_U;

#pragma unroll 4
    for (int lp = 0; lp < PAIRS_PER_FQ / 8; lp++, up += REC_U) {
        ulonglong2 t0 = up[0];   // nx | ny
        ulonglong2 t1 = up[1];   // nz | v0n
        ulonglong2 t2 = up[2];   // CAx | CAy
        ulonglong2 t3 = up[3];   // CAz | eA
        ulonglong2 t4 = up[4];   // CBx | CBy
        ulonglong2 t5 = up[5];   // CBz | eB
        u64 Ev = up[6].x;        // E (f32x2)

        // normal block
        u64 no   = f2fma(t0.x, OX, f2fma(t0.y, OY, f2mul(t1.x, OZ)));
        u64 num  = f2fma(no, NEG1, t1.y);      // v0n - n.o
        u64 den  = f2fma(t0.x, DX, f2fma(t0.y, DY, f2mul(t1.x, DZ)));

        // edge A
        u64 ba = f2fma(t2.x, OX, f2fma(t2.y, OY, f2fma(t3.x, OZ, t3.y)));
        u64 da = f2fma(t2.x, DX, f2fma(t2.y, DY, f2mul(t3.x, DZ)));
        u64 qa = f2fma(ba, den, f2mul(num, da));

        // edge B
        u64 bb_ = f2fma(t4.x, OX, f2fma(t4.y, OY, f2fma(t5.x, OZ, t5.y)));
        u64 db  = f2fma(t4.x, DX, f2fma(t4.y, DY, f2mul(t5.x, DZ)));
        u64 qb  = f2fma(bb_, den, f2mul(num, db));

        // edge C (negated) by identity: C20 = -(C01+C12), e-sum E.
        //   qcn = (ba + bb - E)*den + num*(da+db) = -qc
        // sign(qc)==sign(den)  <=>  sign(qcn)==sign(-den)
        u64 sab = f2add(da, db);
        u64 tab = f2add(ba, bb_);
        u64 nbc = f2fma(Ev, NEG1, tab);               // tab - E
        u64 qcn = f2fma(nbc, den, f2mul(num, sab));

        // w = num - EPS*den
        u64 wv = f2fma(MEPS, den, num);

        unsigned int qa0, qa1, qb0, qb1, qc0, qc1, w0, w1, d0, d1;
        upku(qa, qa0, qa1);
        upku(qb, qb0, qb1);
        upku(qcn, qc0, qc1);
        upku(wv, w0, w1);
        upku(den, d0, d1);

        unsigned int dn0 = d0 ^ SGN, dn1 = d1 ^ SGN;
        unsigned int x0 = ((qa0 ^ d0) | (qb0 ^ d0)) | ((qc0 ^ dn0) | (w0 ^ d0));
        unsigned int x1 = ((qa1 ^ d1) | (qb1 ^ d1)) | ((qc1 ^ dn1) | (w1 ^ d1));
        cnt += (int)(((int)x0 >= 0) & ((d0 & 0x7fffffffu) > EPS_BITS));
        cnt += (int)(((int)x1 >= 0) & ((d1 & 0x7fffffffu) > EPS_BITS));
    }

    s_cnt[wid][lane] = cnt;
    __syncthreads();

    // warp 0 accumulates this block's per-point counts into gmem (int = exact)
    if (wid == 0) {
        int tot = 0;
#pragma unroll
        for (int k = 0; k < 8; k++) tot += s_cnt[k][lane];
        atomicAdd(&g_hits[pt], tot);
    }

    // group completion
    if (tid == 0) {
        __threadfence();
        unsigned int a = atomicAdd(&g_gctr[grp], 1u);
        s_glast = (a == NFQ - 1) ? 1 : 0;
        s_last = 0;
    }
    __syncthreads();

    if (s_glast) {
        if (wid == 0) {
            int tot;
            asm volatile("ld.global.cg.s32 %0, [%1];" : "=r"(tot)
                         : "l"(&g_hits[pt]));
            float dw;
            asm volatile("ld.global.cg.f32 %0, [%1];" : "=f"(dw)
                         : "l"(reinterpret_cast<const float*>(&g_D4[pt]) + 3));
            float pen = (tot & 1) ? dw : 0.0f;
#pragma unroll
            for (int off = 16; off; off >>= 1)
                pen += __shfl_down_sync(~0u, pen, off);
            if (lane == 0) {
                g_part[grp] = pen;
                __threadfence();
                unsigned int a = atomicAdd(&g_ctr, 1u);
                if (a == NGRP - 1) s_last = 1;
            }
        }
        __syncthreads();

        if (s_last) {
            float v;
            asm volatile("ld.global.cg.f32 %0, [%1];" : "=f"(v)
                         : "l"(&g_part[tid]));
            s_red[tid] = v;
            __syncthreads();
#pragma unroll
            for (int off = 128; off; off >>= 1) {
                if (tid < off) s_red[tid] += s_red[tid + off];
                __syncthreads();
            }
            if (tid == 0) out[0] = sqrtf(s_red[0] + 1e-12f);
        }
    }
}

// ---------------- launch ---------------------------------------------------
extern "C" void kernel_launch(void* const* d_in, const int* in_sizes, int n_in,
                              void* d_out, int out_size) {
    const float* obj = (const float*)d_in[0];
    const float* sr  = (const float*)d_in[1];
    const float* hv  = (const float*)d_in[2];
    const float* fn  = (const float*)d_in[3];
    const int*   hf  = (const int*)d_in[4];
    float* out = (float*)d_out;

    sr4_kernel<<<16, 256>>>(sr);
    prep_nn_kernel<<<PREP_BLKS + NN_BLKS, 256>>>(hv, fn, hf, obj, out);
    hits_kernel<<<NGRP * NFQ, 256>>>(obj, out);
}

// round 17
// speedup vs baseline: 1.3311x; 1.0150x over previous
#include <cuda_runtime.h>

// SR_Loss: NN(obj->sr) + ray-triangle parity interior test + reductions.
// obj 8192x3, sr 4096x3, verts 4100x3, normals 4096x3, faces 4096x3.
// Output: [pen_dist, cmap(8192)] = 8193 f32.
//
// 2 kernels (no cross-block handoff anywhere):
//  prep_nn : blocks 0-15 face constants (28 f/pair, edge-C eliminated) +
//            zero counters; blocks 16-527 NN (2 pts/warp) over a block-local
//            smem float4 table {x,y,z,|s|^2} built from raw sr.
//  hits    : 2048 blocks = 256 point-groups x 8 face-slices; 28KB smem slice,
//            f32x2 packed sign tests; int atomics; group-last pen partial;
//            global-last reduces pen_dist.

#define N_OBJ  8192
#define N_SR   4096
#define N_F    4096
#define NPAIR  (N_F / 2)          // 2048
#define EPSF   1e-8f
#define NGRP   (N_OBJ / 32)       // 256 point groups
#define NFQ    8                  // face slices per group
#define PAIRS_PER_FQ (NPAIR / NFQ) // 256

#define REC_U      7                          // ulonglong2 per pair record
#define SLICE_BYTES (PAIRS_PER_FQ * REC_U * 16)  // 28672

#define PREP_BLKS  16
#define NN_BLKS    512

typedef unsigned long long u64;

// ---------------- scratch (device globals; no allocation allowed) ----------
__device__ float4 g_face4[NPAIR * REC_U];   // pair-interleaved records (28 f/pair)
__device__ float4 g_D4[N_OBJ];              // D = trg - o, .w = |D|^2
__device__ int    g_hits[N_OBJ];            // accumulated hit counts
__device__ float  g_part[NGRP];             // per-group pen partials
__device__ unsigned int g_gctr[NGRP];       // per-group arrival counters
__device__ unsigned int g_ctr;              // global arrival counter

// ---------------- f32x2 packed helpers (sm_103a) ---------------------------
__device__ __forceinline__ u64 pk(float lo, float hi) {
    u64 r;
    asm("mov.b64 %0, {%1, %2};" : "=l"(r)
        : "r"(__float_as_uint(lo)), "r"(__float_as_uint(hi)));
    return r;
}
__device__ __forceinline__ void upku(u64 v, unsigned int& lo, unsigned int& hi) {
    asm("mov.b64 {%0, %1}, %2;" : "=r"(lo), "=r"(hi) : "l"(v));
}
__device__ __forceinline__ u64 f2mul(u64 a, u64 b) {
    u64 r;
    asm("mul.rn.f32x2 %0, %1, %2;" : "=l"(r) : "l"(a), "l"(b));
    return r;
}
__device__ __forceinline__ u64 f2add(u64 a, u64 b) {
    u64 r;
    asm("add.rn.f32x2 %0, %1, %2;" : "=l"(r) : "l"(a), "l"(b));
    return r;
}
__device__ __forceinline__ u64 f2fma(u64 a, u64 b, u64 c) {
    u64 r;
    asm("fma.rn.f32x2 %0, %1, %2, %3;" : "=l"(r) : "l"(a), "l"(b), "l"(c));
    return r;
}
__device__ __forceinline__ void cp16(unsigned int saddr, const void* gaddr) {
    asm volatile("cp.async.cg.shared.global [%0], [%1], 16;"
                 :: "r"(saddr), "l"(gaddr));
}
__device__ __forceinline__ unsigned int smem_u32(const void* p) {
    return (unsigned int)__cvta_generic_to_shared(p);
}

// ---------------- prep_nn --------------------------------------------------
// Pair record, 14 slots of f32x2 (28 floats, 112B):
//  q0-2: n, q3: v0.n, q4-6: C01, q7: e01, q8-10: C12, q11: e12,
//  q12: E = e01+e12+e20, q13: pad.   (C20 = -(C01+C12) by identity.)
__global__ void __launch_bounds__(256) prep_nn_kernel(const float* __restrict__ sr,
                                                      const float* __restrict__ hv,
                                                      const float* __restrict__ fn,
                                                      const int*   __restrict__ hf,
                                                      const float* __restrict__ obj,
                                                      float* __restrict__ out) {
    __shared__ float4 s_pack[N_SR];   // 64 KB packed {x,y,z,|s|^2}

    if (blockIdx.x < PREP_BLKS) {
        // ---------------- prep part (no smem use) ---------------------------
        int f = blockIdx.x * 256 + threadIdx.x;   // 0..4095
        if (f == 0) g_ctr = 0;
        if (f < NGRP) g_gctr[f] = 0;
        g_hits[f] = 0;
        g_hits[f + N_F] = 0;

        int i0 = hf[3 * f + 0], i1 = hf[3 * f + 1], i2 = hf[3 * f + 2];
        float nx = fn[3 * f + 0], ny = fn[3 * f + 1], nz = fn[3 * f + 2];
        float v0x = hv[3 * i0 + 0], v0y = hv[3 * i0 + 1], v0z = hv[3 * i0 + 2];
        float v1x = hv[3 * i1 + 0], v1y = hv[3 * i1 + 1], v1z = hv[3 * i1 + 2];
        float v2x = hv[3 * i2 + 0], v2y = hv[3 * i2 + 1], v2z = hv[3 * i2 + 2];

        float vals[14];
        vals[0] = nx; vals[1] = ny; vals[2] = nz;
        vals[3] = v0x * nx + v0y * ny + v0z * nz;

        float eA, eB, eC;
        {   // edge 01
            float wx = v1x - v0x, wy = v1y - v0y, wz = v1z - v0z;
            float cx = ny * wz - nz * wy, cy = nz * wx - nx * wz, cz = nx * wy - ny * wx;
            vals[4] = cx; vals[5] = cy; vals[6] = cz;
            eA = -(v0x * cx + v0y * cy + v0z * cz);
            vals[7] = eA;
        }
        {   // edge 12
            float wx = v2x - v1x, wy = v2y - v1y, wz = v2z - v1z;
            float cx = ny * wz - nz * wy, cy = nz * wx - nx * wz, cz = nx * wy - ny * wx;
            vals[8] = cx; vals[9] = cy; vals[10] = cz;
            eB = -(v1x * cx + v1y * cy + v1z * cz);
            vals[11] = eB;
        }
        {   // edge 20 (only its offset is needed)
            float wx = v0x - v2x, wy = v0y - v2y, wz = v0z - v2z;
            float cx = ny * wz - nz * wy, cy = nz * wx - nx * wz, cz = nx * wy - ny * wx;
            eC = -(v2x * cx + v2y * cy + v2z * cz);
        }
        vals[12] = eA + eB + eC;
        vals[13] = 0.0f;

        int p = f >> 1, h = f & 1;
        float* o = reinterpret_cast<float*>(g_face4) + p * 28 + h;
#pragma unroll
        for (int q = 0; q < 14; q++) o[2 * q] = vals[q];
        return;
    }

    // ---------------- nn part (2 pts/warp; block-local packed sr table) ----
    int tid = threadIdx.x;
    int wid = tid >> 5, lane = tid & 31;
    int pbase = (blockIdx.x - PREP_BLKS) * 16 + wid * 2;

    // stage packed sr: 16 points per thread
#pragma unroll
    for (int k = 0; k < N_SR / 256; k++) {
        int j = tid + k * 256;
        float sx = __ldg(&sr[3 * j + 0]);
        float sy = __ldg(&sr[3 * j + 1]);
        float sz = __ldg(&sr[3 * j + 2]);
        s_pack[j] = make_float4(sx, sy, sz, sx * sx + sy * sy + sz * sz);
    }

    float ox0 = obj[3 * (pbase + 0) + 0], oy0 = obj[3 * (pbase + 0) + 1], oz0 = obj[3 * (pbase + 0) + 2];
    float ox1 = obj[3 * (pbase + 1) + 0], oy1 = obj[3 * (pbase + 1) + 1], oz1 = obj[3 * (pbase + 1) + 2];
    float o20 = ox0 * ox0 + oy0 * oy0 + oz0 * oz0;
    float o21 = ox1 * ox1 + oy1 * oy1 + oz1 * oz1;

    __syncthreads();

    float b0 = 3.402823466e38f, b1 = b0;
    int j0 = 0, j1 = 0;

#pragma unroll 4
    for (int j = lane; j < N_SR; j += 32) {
        float4 s = s_pack[j];
        float d0 = fmaf(-2.0f, ox0 * s.x + fmaf(oy0, s.y, oz0 * s.z), o20 + s.w);
        float d1 = fmaf(-2.0f, ox1 * s.x + fmaf(oy1, s.y, oz1 * s.z), o21 + s.w);
        if (d0 < b0) { b0 = d0; j0 = j; }
        if (d1 < b1) { b1 = d1; j1 = j; }
    }
#pragma unroll
    for (int off = 16; off; off >>= 1) {
        float t; int tj;
        t = __shfl_down_sync(~0u, b0, off); tj = __shfl_down_sync(~0u, j0, off);
        if (t < b0 || (t == b0 && tj < j0)) { b0 = t; j0 = tj; }
        t = __shfl_down_sync(~0u, b1, off); tj = __shfl_down_sync(~0u, j1, off);
        if (t < b1 || (t == b1 && tj < j1)) { b1 = t; j1 = tj; }
    }

    if (lane == 0) {
        float obx[2] = {ox0, ox1};
        float oby[2] = {oy0, oy1};
        float obz[2] = {oz0, oz1};
        float bb[2] = {b0, b1};
        int   jj[2] = {j0, j1};
#pragma unroll
        for (int k = 0; k < 2; k++) {
            float4 s = s_pack[jj[k]];
            float Dx = s.x - obx[k], Dy = s.y - oby[k], Dz = s.z - obz[k];
            g_D4[pbase + k] = make_float4(Dx, Dy, Dz, Dx * Dx + Dy * Dy + Dz * Dz);
            float nnd = sqrtf(fmaxf(bb[k], 0.0f));
            out[1 + pbase + k] = 2.0f / (1.0f + expf(100.0f * nnd));
        }
    }
}

// ---------------- hits: parity + reductions --------------------------------
// Block = (group, slice): 32 points (lane=point) x 256 face-pairs.
// Whole slice (28 KB) staged once; single __syncthreads before compute.
__global__ void __launch_bounds__(256, 5) hits_kernel(const float* __restrict__ obj,
                                                      float* __restrict__ out) {
    __shared__ __align__(16) char s_face[SLICE_BYTES];   // 28 KB
    __shared__ int    s_cnt[8][32];
    __shared__ int    s_glast, s_last;
    __shared__ float  s_red[256];

    int tid = threadIdx.x;
    int wid = tid >> 5, lane = tid & 31;
    int grp = blockIdx.x >> 3, fq = blockIdx.x & 7;
    int pt  = grp * 32 + lane;

    // stage whole slice: 1792 chunks, 7 per thread
    {
        const char* gfb = reinterpret_cast<const char*>(g_face4)
                          + (size_t)fq * SLICE_BYTES;
        unsigned int sb = smem_u32(&s_face[0]);
#pragma unroll
        for (int k = 0; k < 7; k++) {
            int idx = tid + k * 256;
            cp16(sb + idx * 16, gfb + idx * 16);
        }
        asm volatile("cp.async.commit_group;" ::: "memory");
    }

    float ox = obj[3 * pt + 0], oy = obj[3 * pt + 1], oz = obj[3 * pt + 2];
    float4 D = __ldg(&g_D4[pt]);

    u64 OX = pk(ox, ox), OY = pk(oy, oy), OZ = pk(oz, oz);
    u64 DX = pk(D.x, D.x), DY = pk(D.y, D.y), DZ = pk(D.z, D.z);
    u64 NEG1 = pk(-1.0f, -1.0f);
    u64 MEPS = pk(-EPSF, -EPSF);
    const unsigned int EPS_BITS = __float_as_uint(EPSF);
    const unsigned int SGN = 0x80000000u;

    asm volatile("cp.async.wait_group 0;" ::: "memory");
    __syncthreads();

    int cnt = 0;
    const ulonglong2* up = reinterpret_cast<const ulonglong2*>(&s_face[0])
                           + (wid * (PAIRS_PER_FQ / 8)) * REC_U;

#pragma unroll 4
    for (int lp = 0; lp < PAIRS_PER_FQ / 8; lp++, up += REC_U) {
        ulonglong2 t0 = up[0];   // nx | ny
        ulonglong2 t1 = up[1];   // nz | v0n
        ulonglong2 t2 = up[2];   // CAx | CAy
        ulonglong2 t3 = up[3];   // CAz | eA
        ulonglong2 t4 = up[4];   // CBx | CBy
        ulonglong2 t5 = up[5];   // CBz | eB
        u64 Ev = up[6].x;        // E (f32x2)

        // normal block
        u64 no   = f2fma(t0.x, OX, f2fma(t0.y, OY, f2mul(t1.x, OZ)));
        u64 num  = f2fma(no, NEG1, t1.y);      // v0n - n.o
        u64 den  = f2fma(t0.x, DX, f2fma(t0.y, DY, f2mul(t1.x, DZ)));

        // edge A
        u64 ba = f2fma(t2.x, OX, f2fma(t2.y, OY, f2fma(t3.x, OZ, t3.y)));
        u64 da = f2fma(t2.x, DX, f2fma(t2.y, DY, f2mul(t3.x, DZ)));
        u64 qa = f2fma(ba, den, f2mul(num, da));

        // edge B
        u64 bb_ = f2fma(t4.x, OX, f2fma(t4.y, OY, f2fma(t5.x, OZ, t5.y)));
        u64 db  = f2fma(t4.x, DX, f2fma(t4.y, DY, f2mul(t5.x, DZ)));
        u64 qb  = f2fma(bb_, den, f2mul(num, db));

        // edge C (negated) by identity: C20 = -(C01+C12), e-sum E.
        //   qcn = (ba + bb - E)*den + num*(da+db) = -qc
        // sign(qc)==sign(den)  <=>  sign(qcn)==sign(-den)
        u64 sab = f2add(da, db);
        u64 tab = f2add(ba, bb_);
        u64 nbc = f2fma(Ev, NEG1, tab);               // tab - E
        u64 qcn = f2fma(nbc, den, f2mul(num, sab));

        // w = num - EPS*den
        u64 wv = f2fma(MEPS, den, num);

        unsigned int qa0, qa1, qb0, qb1, qc0, qc1, w0, w1, d0, d1;
        upku(qa, qa0, qa1);
        upku(qb, qb0, qb1);
        upku(qcn, qc0, qc1);
        upku(wv, w0, w1);
        upku(den, d0, d1);

        unsigned int dn0 = d0 ^ SGN, dn1 = d1 ^ SGN;
        unsigned int x0 = ((qa0 ^ d0) | (qb0 ^ d0)) | ((qc0 ^ dn0) | (w0 ^ d0));
        unsigned int x1 = ((qa1 ^ d1) | (qb1 ^ d1)) | ((qc1 ^ dn1) | (w1 ^ d1));
        cnt += (int)(((int)x0 >= 0) & ((d0 & 0x7fffffffu) > EPS_BITS));
        cnt += (int)(((int)x1 >= 0) & ((d1 & 0x7fffffffu) > EPS_BITS));
    }

    s_cnt[wid][lane] = cnt;
    __syncthreads();

    // warp 0 accumulates this block's per-point counts into gmem (int = exact)
    if (wid == 0) {
        int tot = 0;
#pragma unroll
        for (int k = 0; k < 8; k++) tot += s_cnt[k][lane];
        atomicAdd(&g_hits[pt], tot);
    }

    // group completion
    if (tid == 0) {
        __threadfence();
        unsigned int a = atomicAdd(&g_gctr[grp], 1u);
        s_glast = (a == NFQ - 1) ? 1 : 0;
        s_last = 0;
    }
    __syncthreads();

    if (s_glast) {
        if (wid == 0) {
            int tot;
            asm volatile("ld.global.cg.s32 %0, [%1];" : "=r"(tot)
                         : "l"(&g_hits[pt]));
            float dw;
            asm volatile("ld.global.cg.f32 %0, [%1];" : "=f"(dw)
                         : "l"(reinterpret_cast<const float*>(&g_D4[pt]) + 3));
            float pen = (tot & 1) ? dw : 0.0f;
#pragma unroll
            for (int off = 16; off; off >>= 1)
                pen += __shfl_down_sync(~0u, pen, off);
            if (lane == 0) {
                g_part[grp] = pen;
                __threadfence();
                unsigned int a = atomicAdd(&g_ctr, 1u);
                if (a == NGRP - 1) s_last = 1;
            }
        }
        __syncthreads();

        if (s_last) {
            float v;
            asm volatile("ld.global.cg.f32 %0, [%1];" : "=f"(v)
                         : "l"(&g_part[tid]));
            s_red[tid] = v;
            __syncthreads();
#pragma unroll
            for (int off = 128; off; off >>= 1) {
                if (tid < off) s_red[tid] += s_red[tid + off];
                __syncthreads();
            }
            if (tid == 0) out[0] = sqrtf(s_red[0] + 1e-12f);
        }
    }
}

// ---------------- launch ---------------------------------------------------
extern "C" void kernel_launch(void* const* d_in, const int* in_sizes, int n_in,
                              void* d_out, int out_size) {
    const float* obj = (const float*)d_in[0];
    const float* sr  = (const float*)d_in[1];
    const float* hv  = (const float*)d_in[2];
    const float* fn  = (const float*)d_in[3];
    const int*   hf  = (const int*)d_in[4];
    float* out = (float*)d_out;

    prep_nn_kernel<<<PREP_BLKS + NN_BLKS, 256>>>(sr, hv, fn, hf, obj, out);
    hits_kernel<<<NGRP * NFQ, 256>>>(obj, out);
}